// round 4
// baseline (speedup 1.0000x reference)
#include <cuda_runtime.h>
#include <cstdint>

// N=100000 nodes, D=64 feats, E=1250000 edges, W=1024, T=20000 targets.
static constexpr int N_NODES = 100000;
static constexpr int D  = 64;
static constexpr int D4 = 16;       // float4 per row
static constexpr int CAP = 64;      // per-node bin capacity (P(deg>=64) ~ 1e-23)

// Scratch. __device__ globals start zero-initialized; the accumulate kernel
// resets count/flag in its epilogue, preserving the invariant across replays.
__device__ int  g_count[N_NODES];
__device__ int  g_flag[N_NODES];
__device__ int2 g_bins[(size_t)N_NODES * CAP];   // {src, widx}

// ---------------------------------------------------------------------------
// K1: bin edges by destination (2 edges per thread, vectorized loads);
// low-index threads also set target flags (2 per thread).
// ---------------------------------------------------------------------------
__global__ void scatter_kernel(const int* __restrict__ u,
                               const int* __restrict__ v,
                               const int* __restrict__ widx,
                               const int* __restrict__ targets,
                               int n_edges, int n_targets) {
    int t = blockIdx.x * blockDim.x + threadIdx.x;
    int e = t * 2;
    if (e >= n_edges) return;

    // flags: first n_targets/2 threads handle 2 targets each
    int ti = t * 2;
    if (ti + 1 < n_targets) {
        int2 tg = *(const int2*)(targets + ti);
        g_flag[tg.x] = 1;
        g_flag[tg.y] = 1;
    } else if (ti < n_targets) {
        g_flag[targets[ti]] = 1;
    }

    if (e + 1 < n_edges) {
        int2 uu = *(const int2*)(u + e);
        int2 vv = *(const int2*)(v + e);
        int2 ww = *(const int2*)(widx + e);
        int p0 = atomicAdd(&g_count[vv.x], 1);
        if (p0 < CAP) g_bins[(size_t)vv.x * CAP + p0] = make_int2(uu.x, ww.x);
        int p1 = atomicAdd(&g_count[vv.y], 1);
        if (p1 < CAP) g_bins[(size_t)vv.y * CAP + p1] = make_int2(uu.y, ww.y);
    } else {
        int dst = v[e];
        int p = atomicAdd(&g_count[dst], 1);
        if (p < CAP) g_bins[(size_t)dst * CAP + p] = make_int2(u[e], widx[e]);
    }
}

// ---------------------------------------------------------------------------
// K2: one node per HALF-WARP (2 nodes per warp). Each 16-lane half owns its
// node's full edge list: unroll-4 main loop (~3 iterations at deg~12.5) with
// next-iteration bin prefetch. No cross-half reduction. Epilogue: add old_x
// unless target, single coalesced 256B row write, reset count+flag.
// ---------------------------------------------------------------------------
__global__ void accumulate_kernel(const float4* __restrict__ x4,
                                  const float4* __restrict__ w4,
                                  float4* __restrict__ out4) {
    int warp = (blockIdx.x * blockDim.x + threadIdx.x) >> 5;
    int lane = threadIdx.x & 31;
    int half = lane >> 4;
    int l16  = lane & 15;

    int n = warp * 2 + half;
    if (n >= N_NODES) return;

    int deg = g_count[n];
    if (deg > CAP) deg = CAP;
    const int2* __restrict__ bins = g_bins + (size_t)n * CAP;

    float4 acc = make_float4(0.f, 0.f, 0.f, 0.f);

    int i = 0;
    if (i + 4 <= deg) {
        // prologue load
        int2 e0 = bins[0], e1 = bins[1], e2 = bins[2], e3 = bins[3];
        for (;;) {
            float4 xa = x4[(size_t)e0.x * D4 + l16];
            float4 wa = w4[(size_t)e0.y * D4 + l16];
            float4 xb = x4[(size_t)e1.x * D4 + l16];
            float4 wb = w4[(size_t)e1.y * D4 + l16];
            float4 xc = x4[(size_t)e2.x * D4 + l16];
            float4 wc = w4[(size_t)e2.y * D4 + l16];
            float4 xd = x4[(size_t)e3.x * D4 + l16];
            float4 wd = w4[(size_t)e3.y * D4 + l16];

            i += 4;
            bool more = (i + 4 <= deg);
            int2 f0, f1, f2, f3;
            if (more) {             // prefetch next batch before the FMAs
                f0 = bins[i];     f1 = bins[i + 1];
                f2 = bins[i + 2]; f3 = bins[i + 3];
            }

            acc.x += xa.x * wa.x; acc.y += xa.y * wa.y; acc.z += xa.z * wa.z; acc.w += xa.w * wa.w;
            acc.x += xb.x * wb.x; acc.y += xb.y * wb.y; acc.z += xb.z * wb.z; acc.w += xb.w * wb.w;
            acc.x += xc.x * wc.x; acc.y += xc.y * wc.y; acc.z += xc.z * wc.z; acc.w += xc.w * wc.w;
            acc.x += xd.x * wd.x; acc.y += xd.y * wd.y; acc.z += xd.z * wd.z; acc.w += xd.w * wd.w;

            if (!more) break;
            e0 = f0; e1 = f1; e2 = f2; e3 = f3;
        }
    }
    // remainder (0-3 edges), pairwise for some MLP
    if (i + 2 <= deg) {
        int2 e0 = bins[i], e1 = bins[i + 1];
        float4 xa = x4[(size_t)e0.x * D4 + l16];
        float4 wa = w4[(size_t)e0.y * D4 + l16];
        float4 xb = x4[(size_t)e1.x * D4 + l16];
        float4 wb = w4[(size_t)e1.y * D4 + l16];
        acc.x += xa.x * wa.x; acc.y += xa.y * wa.y; acc.z += xa.z * wa.z; acc.w += xa.w * wa.w;
        acc.x += xb.x * wb.x; acc.y += xb.y * wb.y; acc.z += xb.z * wb.z; acc.w += xb.w * wb.w;
        i += 2;
    }
    if (i < deg) {
        int2 e0 = bins[i];
        float4 xa = x4[(size_t)e0.x * D4 + l16];
        float4 wa = w4[(size_t)e0.y * D4 + l16];
        acc.x += xa.x * wa.x; acc.y += xa.y * wa.y; acc.z += xa.z * wa.z; acc.w += xa.w * wa.w;
    }

    if (!g_flag[n]) {
        float4 xn = x4[(size_t)n * D4 + l16];
        acc.x += xn.x; acc.y += xn.y; acc.z += xn.z; acc.w += xn.w;
    }
    out4[(size_t)n * D4 + l16] = acc;

    if (l16 == 0) {          // reset scratch for the next replay
        g_count[n] = 0;
        g_flag[n]  = 0;
    }
}

// ---------------------------------------------------------------------------
extern "C" void kernel_launch(void* const* d_in, const int* in_sizes, int n_in,
                              void* d_out, int out_size) {
    const float* x       = (const float*)d_in[0];
    const float* weights = (const float*)d_in[1];
    const int*   u       = (const int*)d_in[2];
    const int*   v       = (const int*)d_in[3];
    const int*   widx    = (const int*)d_in[4];
    const int*   targets = (const int*)d_in[5];
    float* out = (float*)d_out;

    int n_edges   = in_sizes[2];
    int n_targets = in_sizes[5];

    {
        int work = (n_edges + 1) / 2;
        int threads = 256;
        int blocks = (work + threads - 1) / threads;
        scatter_kernel<<<blocks, threads>>>(u, v, widx, targets,
                                            n_edges, n_targets);
    }
    {
        // 2 nodes per warp -> ceil(N/2) warps
        long long total_threads = ((long long)(N_NODES + 1) / 2) * 32;
        int threads = 256;
        int blocks = (int)((total_threads + threads - 1) / threads);
        accumulate_kernel<<<blocks, threads>>>((const float4*)x,
                                               (const float4*)weights,
                                               (float4*)out);
    }
}

// round 5
// speedup vs baseline: 1.0598x; 1.0598x over previous
#include <cuda_runtime.h>
#include <cstdint>

// N=100000 nodes, D=64 feats, E=1250000 edges, W=1024, T=20000 targets.
static constexpr int N_NODES = 100000;
static constexpr int D2 = 32;       // float2 per row (64 floats)
static constexpr int CAP = 64;      // per-node bin capacity (P(deg>=64) ~ 1e-23)

// Packed edge entry: src in bits [0,17), widx in bits [17,27).
static constexpr int SRC_BITS = 17;
static constexpr unsigned SRC_MASK = (1u << SRC_BITS) - 1u;

// Scratch. __device__ globals start zero-initialized; the accumulate kernel
// resets count/flag in its epilogue, preserving the invariant across replays.
__device__ int      g_count[N_NODES];
__device__ int      g_flag[N_NODES];
__device__ unsigned g_bins[(size_t)N_NODES * CAP];   // packed (widx<<17)|src

// ---------------------------------------------------------------------------
// K1: bin edges by destination (2 edges per thread, vectorized loads);
// low-index threads also set target flags.
// ---------------------------------------------------------------------------
__global__ void scatter_kernel(const int* __restrict__ u,
                               const int* __restrict__ v,
                               const int* __restrict__ widx,
                               const int* __restrict__ targets,
                               int n_edges, int n_targets) {
    int t = blockIdx.x * blockDim.x + threadIdx.x;
    int e = t * 2;
    if (e >= n_edges) return;

    int ti = t * 2;
    if (ti + 1 < n_targets) {
        int2 tg = *(const int2*)(targets + ti);
        g_flag[tg.x] = 1;
        g_flag[tg.y] = 1;
    } else if (ti < n_targets) {
        g_flag[targets[ti]] = 1;
    }

    if (e + 1 < n_edges) {
        int2 uu = *(const int2*)(u + e);
        int2 vv = *(const int2*)(v + e);
        int2 ww = *(const int2*)(widx + e);
        unsigned c0 = ((unsigned)ww.x << SRC_BITS) | (unsigned)uu.x;
        unsigned c1 = ((unsigned)ww.y << SRC_BITS) | (unsigned)uu.y;
        int p0 = atomicAdd(&g_count[vv.x], 1);
        if (p0 < CAP) g_bins[(size_t)vv.x * CAP + p0] = c0;
        int p1 = atomicAdd(&g_count[vv.y], 1);
        if (p1 < CAP) g_bins[(size_t)vv.y * CAP + p1] = c1;
    } else {
        unsigned c = ((unsigned)widx[e] << SRC_BITS) | (unsigned)u[e];
        int dst = v[e];
        int p = atomicAdd(&g_count[dst], 1);
        if (p < CAP) g_bins[(size_t)dst * CAP + p] = c;
    }
}

// ---------------------------------------------------------------------------
// K2: one node per FULL warp; each lane owns one float2 (8B) slice of the
// 64-float row. All 32 lanes process every edge together -> fully convergent
// loop (deg ~12.5, unroll-4 main loop ~3 iterations). Bin metadata for 4
// edges arrives in a single int4 load. Epilogue: add old_x unless target,
// one coalesced 256B row write, reset count+flag for the next replay.
// ---------------------------------------------------------------------------
__global__ void __launch_bounds__(256)
accumulate_kernel(const float2* __restrict__ x2,
                  const float2* __restrict__ w2,
                  float2* __restrict__ out2) {
    int warp = (blockIdx.x * blockDim.x + threadIdx.x) >> 5;
    int lane = threadIdx.x & 31;
    if (warp >= N_NODES) return;
    int n = warp;

    int deg = g_count[n];
    if (deg > CAP) deg = CAP;
    const unsigned* __restrict__ bins = g_bins + (size_t)n * CAP;

    float2 acc = make_float2(0.f, 0.f);

    int i = 0;
    for (; i + 4 <= deg; i += 4) {
        int4 b = *(const int4*)(bins + i);          // 4 packed edges, aligned
        unsigned c0 = (unsigned)b.x, c1 = (unsigned)b.y;
        unsigned c2 = (unsigned)b.z, c3 = (unsigned)b.w;
        float2 xa = x2[(size_t)(c0 & SRC_MASK) * D2 + lane];
        float2 wa = w2[(size_t)(c0 >> SRC_BITS)  * D2 + lane];
        float2 xb = x2[(size_t)(c1 & SRC_MASK) * D2 + lane];
        float2 wb = w2[(size_t)(c1 >> SRC_BITS)  * D2 + lane];
        float2 xc = x2[(size_t)(c2 & SRC_MASK) * D2 + lane];
        float2 wc = w2[(size_t)(c2 >> SRC_BITS)  * D2 + lane];
        float2 xd = x2[(size_t)(c3 & SRC_MASK) * D2 + lane];
        float2 wd = w2[(size_t)(c3 >> SRC_BITS)  * D2 + lane];
        acc.x += xa.x * wa.x; acc.y += xa.y * wa.y;
        acc.x += xb.x * wb.x; acc.y += xb.y * wb.y;
        acc.x += xc.x * wc.x; acc.y += xc.y * wc.y;
        acc.x += xd.x * wd.x; acc.y += xd.y * wd.y;
    }
    if (i + 2 <= deg) {                              // pairwise remainder
        unsigned c0 = bins[i], c1 = bins[i + 1];
        float2 xa = x2[(size_t)(c0 & SRC_MASK) * D2 + lane];
        float2 wa = w2[(size_t)(c0 >> SRC_BITS)  * D2 + lane];
        float2 xb = x2[(size_t)(c1 & SRC_MASK) * D2 + lane];
        float2 wb = w2[(size_t)(c1 >> SRC_BITS)  * D2 + lane];
        acc.x += xa.x * wa.x; acc.y += xa.y * wa.y;
        acc.x += xb.x * wb.x; acc.y += xb.y * wb.y;
        i += 2;
    }
    if (i < deg) {
        unsigned c0 = bins[i];
        float2 xa = x2[(size_t)(c0 & SRC_MASK) * D2 + lane];
        float2 wa = w2[(size_t)(c0 >> SRC_BITS)  * D2 + lane];
        acc.x += xa.x * wa.x; acc.y += xa.y * wa.y;
    }

    if (!g_flag[n]) {
        float2 xn = x2[(size_t)n * D2 + lane];
        acc.x += xn.x; acc.y += xn.y;
    }
    out2[(size_t)n * D2 + lane] = acc;

    if (lane == 0) {         // reset scratch for the next replay
        g_count[n] = 0;
        g_flag[n]  = 0;
    }
}

// ---------------------------------------------------------------------------
extern "C" void kernel_launch(void* const* d_in, const int* in_sizes, int n_in,
                              void* d_out, int out_size) {
    const float* x       = (const float*)d_in[0];
    const float* weights = (const float*)d_in[1];
    const int*   u       = (const int*)d_in[2];
    const int*   v       = (const int*)d_in[3];
    const int*   widx    = (const int*)d_in[4];
    const int*   targets = (const int*)d_in[5];
    float* out = (float*)d_out;

    int n_edges   = in_sizes[2];
    int n_targets = in_sizes[5];

    {
        int work = (n_edges + 1) / 2;
        int threads = 256;
        int blocks = (work + threads - 1) / threads;
        scatter_kernel<<<blocks, threads>>>(u, v, widx, targets,
                                            n_edges, n_targets);
    }
    {
        long long total_threads = (long long)N_NODES * 32;   // warp per node
        int threads = 256;
        int blocks = (int)((total_threads + threads - 1) / threads);
        accumulate_kernel<<<blocks, threads>>>((const float2*)x,
                                               (const float2*)weights,
                                               (float2*)out);
    }
}